// round 15
// baseline (speedup 1.0000x reference)
#include <cuda_runtime.h>
#include <math.h>
#include <stdint.h>

#define B_   16
#define C_   512
#define L_   1024
#define NH_  8
#define HD_  64
#define NG_  32
#define GCH_ 16
#define M_QKV 1536
#define EPS_ 1e-5f
#define SCQ  0.1803368801111204f   // 0.125 * log2(e)

// Scratch (device globals)
__device__ uint16_t g_h   [(size_t)B_ * L_ * C_];     // groupnorm out bf16 [B][L][C]
__device__ uint16_t g_qkvh[(size_t)B_ * M_QKV * L_];  // qkv [B][3C][L]: Q,K bf16 / V f16
__device__ uint16_t g_at  [(size_t)B_ * L_ * C_];     // attention out bf16 [B][L][C]
__device__ uint16_t g_wq  [(size_t)M_QKV * C_];       // qkv_w bf16
__device__ uint16_t g_wp  [(size_t)C_ * C_];          // proj_w bf16

__device__ __forceinline__ uint32_t smem_u32(const void* p){
    uint32_t a;
    asm("{ .reg .u64 t; cvta.to.shared.u64 t, %1; cvt.u32.u64 %0, t; }" : "=r"(a) : "l"(p));
    return a;
}
__device__ __forceinline__ uint32_t f2bf2(float lo, float hi){
    uint32_t r; asm("cvt.rn.bf16x2.f32 %0, %1, %2;" : "=r"(r) : "f"(hi), "f"(lo)); return r;
}
__device__ __forceinline__ uint32_t f2h2(float lo, float hi){
    uint32_t r; asm("cvt.rn.f16x2.f32 %0, %1, %2;" : "=r"(r) : "f"(hi), "f"(lo)); return r;
}
__device__ __forceinline__ uint32_t ex2h2(uint32_t x){
    uint32_t r; asm("ex2.approx.f16x2 %0, %1;" : "=r"(r) : "r"(x)); return r;
}
__device__ __forceinline__ void ldsm_x4(uint32_t* r, uint32_t addr){
    asm volatile("ldmatrix.sync.aligned.m8n8.x4.shared.b16 {%0,%1,%2,%3}, [%4];"
        : "=r"(r[0]), "=r"(r[1]), "=r"(r[2]), "=r"(r[3]) : "r"(addr));
}
__device__ __forceinline__ void ldsm_x4_t(uint32_t* r, uint32_t addr){
    asm volatile("ldmatrix.sync.aligned.m8n8.x4.trans.shared.b16 {%0,%1,%2,%3}, [%4];"
        : "=r"(r[0]), "=r"(r[1]), "=r"(r[2]), "=r"(r[3]) : "r"(addr));
}
__device__ __forceinline__ void mma_bf16(float* d, const uint32_t* a,
                                         uint32_t b0, uint32_t b1){
    asm volatile(
        "mma.sync.aligned.m16n8k16.row.col.f32.bf16.bf16.f32 "
        "{%0,%1,%2,%3}, {%4,%5,%6,%7}, {%8,%9}, {%0,%1,%2,%3};"
        : "+f"(d[0]), "+f"(d[1]), "+f"(d[2]), "+f"(d[3])
        : "r"(a[0]), "r"(a[1]), "r"(a[2]), "r"(a[3]), "r"(b0), "r"(b1));
}
__device__ __forceinline__ void mma_f16(float* d, const uint32_t* a,
                                        uint32_t b0, uint32_t b1){
    asm volatile(
        "mma.sync.aligned.m16n8k16.row.col.f32.f16.f16.f32 "
        "{%0,%1,%2,%3}, {%4,%5,%6,%7}, {%8,%9}, {%0,%1,%2,%3};"
        : "+f"(d[0]), "+f"(d[1]), "+f"(d[2]), "+f"(d[3])
        : "r"(a[0]), "r"(a[1]), "r"(a[2]), "r"(a[3]), "r"(b0), "r"(b1));
}
#define CP16(dst, src) \
    asm volatile("cp.async.cg.shared.global [%0], [%1], 16;" :: "r"(dst), "l"(src))
#define CP_COMMIT() asm volatile("cp.async.commit_group;" ::: "memory")
#define CP_WAIT1()  asm volatile("cp.async.wait_group 1;" ::: "memory")
#define CP_WAIT0()  asm volatile("cp.async.wait_group 0;" ::: "memory")

// ---------------------------------------------------------------------------
// Fused GroupNorm (single global pass, smem-cached) + weight conversion.
// ---------------------------------------------------------------------------
#define N4Q (M_QKV * C_ / 4)
#define N4P (C_ * C_ / 4)
#define GNP 257
#define GN_SMEM (16 * GNP * 16)

__global__ void gn_kernel(const float* __restrict__ x,
                          const float* __restrict__ w,
                          const float* __restrict__ bn,
                          const float* __restrict__ qkv_w,
                          const float* __restrict__ proj_w)
{
    int tid = threadIdx.x;
    if (blockIdx.x >= 512) {
        int i = (blockIdx.x - 512) * 256 + tid;
        const float4* src;
        uint2* dst;
        if (i < N4Q) { src = (const float4*)qkv_w + i;        dst = (uint2*)g_wq + i; }
        else         { src = (const float4*)proj_w + (i-N4Q); dst = (uint2*)g_wp + (i-N4Q); }
        float4 v = *src;
        uint2 o;
        o.x = f2bf2(v.x, v.y);
        o.y = f2bf2(v.z, v.w);
        *dst = o;
        return;
    }

    extern __shared__ float xs[];
    float4* xs4 = (float4*)xs;

    int gb  = blockIdx.x;
    int b   = gb >> 5;
    int grp = gb & 31;
    const float4* xp4 = (const float4*)(x + ((size_t)b * C_ + (size_t)grp * GCH_) * L_);

    float s = 0.f, s2 = 0.f;
#pragma unroll 4
    for (int i = tid; i < 4096; i += 256) {
        float4 v = xp4[i];
        xs4[(i >> 8) * GNP + (i & 255)] = v;
        s  += v.x + v.y + v.z + v.w;
        s2 += v.x*v.x + v.y*v.y + v.z*v.z + v.w*v.w;
    }
    __shared__ float sh[512];
    sh[tid] = s; sh[256 + tid] = s2;
    __syncthreads();
    for (int off = 128; off > 0; off >>= 1) {
        if (tid < off) { sh[tid] += sh[tid + off]; sh[256 + tid] += sh[256 + tid + off]; }
        __syncthreads();
    }
    __shared__ float sA[16], sB[16];
    if (tid == 0) {
        float mean = sh[0] * (1.f / (GCH_ * L_));
        float var  = sh[256] * (1.f / (GCH_ * L_)) - mean * mean;
        sh[0] = mean;
        sh[1] = rsqrtf(var + EPS_);
    }
    __syncthreads();
    if (tid < 16) {
        float mean = sh[0], inv = sh[1];
        float wc = w[grp * GCH_ + tid], bc = bn[grp * GCH_ + tid];
        sA[tid] = inv * wc;
        sB[tid] = bc - mean * inv * wc;
    }
    __syncthreads();

#pragma unroll
    for (int t = 0; t < 16; t++) {
        int idx = tid + t * 256;
        int l = idx >> 2, cq = idx & 3;
        int c0 = cq * 4;
        float v0 = xs[(c0+0) * (GNP*4) + l] * sA[c0+0] + sB[c0+0];
        float v1 = xs[(c0+1) * (GNP*4) + l] * sA[c0+1] + sB[c0+1];
        float v2 = xs[(c0+2) * (GNP*4) + l] * sA[c0+2] + sB[c0+2];
        float v3 = xs[(c0+3) * (GNP*4) + l] * sA[c0+3] + sB[c0+3];
        uint2 o;
        o.x = f2bf2(v0, v1);
        o.y = f2bf2(v2, v3);
        *(uint2*)&g_h[((size_t)b * L_ + l) * C_ + grp * GCH_ + c0] = o;
    }
}

// ---------------------------------------------------------------------------
// bf16 GEMM, BK=64, 3-stage cp.async (wait_group 1 → depth-2 latency hiding),
// 256 threads = 8 warps (2m x 4n).
// MODE 0 (qkv): region stores — Q scaled bf16 / K bf16 / V f16.
// MODE 1 (proj): fp32 + residual.
// ---------------------------------------------------------------------------
#define GP 72
#define GSTG (128 * GP)
#define STAGE_B (2 * GSTG * 2)            // 36864 bytes per stage
#define GSMEM_BYTES (3 * STAGE_B)         // 110592

template <int MODE>
__device__ __forceinline__ void gemm_mma(const uint16_t* __restrict__ Aw,
                                         const float* __restrict__ bias,
                                         const uint16_t* __restrict__ Bg,
                                         const float* __restrict__ res,
                                         float* __restrict__ Cf,
                                         uint16_t* __restrict__ Ch)
{
    extern __shared__ uint16_t smh[];
    uint32_t smb = smem_u32(smh);
    int tid  = threadIdx.x;
    int wid  = tid >> 5, lane = tid & 31;
    int g    = lane >> 2, t4 = lane & 3;
    int wm   = wid & 1;
    int wn   = wid >> 1;
    int o0   = blockIdx.y * 128;
    int l0   = blockIdx.x * 128;
    int mb   = wm * 64;
    int nb   = wn * 32;
    int l15  = lane & 15;
    int khal = (lane >> 4) * 16;

    float acc[4][4][4];
#pragma unroll
    for (int mt = 0; mt < 4; mt++)
#pragma unroll
        for (int nt = 0; nt < 4; nt++)
#pragma unroll
            for (int r = 0; r < 4; r++) acc[mt][nt][r] = 0.f;

    auto issue = [&](int st, int c0) {
        uint32_t base = smb + st * STAGE_B;
#pragma unroll
        for (int t = 0; t < 4; t++) {
            int idx = tid + t * 256;
            int row = idx >> 3, c = idx & 7;
            CP16(base + row * 144 + c * 16,
                 &Aw[(size_t)(o0 + row) * C_ + c0 + c * 8]);
            CP16(base + GSTG * 2 + row * 144 + c * 16,
                 &Bg[(size_t)(l0 + row) * C_ + c0 + c * 8]);
        }
    };

    issue(0, 0);   CP_COMMIT();
    issue(1, 64);  CP_COMMIT();

    for (int it = 0; it < 8; ++it) {
        if (it < 7) CP_WAIT1(); else CP_WAIT0();
        __syncthreads();
        if (it + 2 < 8) { issue((it + 2) % 3, (it + 2) * 64); CP_COMMIT(); }

        uint32_t AsB = smb + (it % 3) * STAGE_B;
        uint32_t BsB = AsB + GSTG * 2;
#pragma unroll
        for (int ks = 0; ks < 4; ks++) {
            int kb = ks * 32 + khal;
            uint32_t af[4][4];
#pragma unroll
            for (int mt = 0; mt < 4; mt++)
                ldsm_x4(af[mt], AsB + (mb + mt * 16 + l15) * 144 + kb);
            uint32_t bf[4][2];
#pragma unroll
            for (int ng = 0; ng < 2; ng++) {
                uint32_t rr[4];
                ldsm_x4(rr, BsB + (nb + ng * 16 + l15) * 144 + kb);
                bf[2*ng][0]   = rr[0]; bf[2*ng][1]   = rr[2];
                bf[2*ng+1][0] = rr[1]; bf[2*ng+1][1] = rr[3];
            }
#pragma unroll
            for (int mt = 0; mt < 4; mt++)
#pragma unroll
                for (int nt = 0; nt < 4; nt++)
                    mma_bf16(acc[mt][nt], af[mt], bf[nt][0], bf[nt][1]);
        }
    }

    int region = o0 >> 9;     // qkv: 0=Q, 1=K, 2=V
    float qscale = (MODE == 0 && region == 0) ? SCQ : 1.f;

#pragma unroll
    for (int mt = 0; mt < 4; mt++) {
        int r0 = o0 + mb + mt * 16 + g;
        int r1 = r0 + 8;
        float bv0 = bias[r0], bv1 = bias[r1];
#pragma unroll
        for (int nt = 0; nt < 4; nt++) {
            int col = l0 + nb + nt * 8 + 2 * t4;
            size_t a0 = (size_t)r0 * L_ + col;
            size_t a1 = (size_t)r1 * L_ + col;
            float v00 = acc[mt][nt][0] + bv0, v01 = acc[mt][nt][1] + bv0;
            float v10 = acc[mt][nt][2] + bv1, v11 = acc[mt][nt][3] + bv1;
            if (MODE == 0) {
                if (region == 2) {
                    *(uint32_t*)&Ch[a0] = f2h2(v00, v01);
                    *(uint32_t*)&Ch[a1] = f2h2(v10, v11);
                } else {
                    v00 *= qscale; v01 *= qscale; v10 *= qscale; v11 *= qscale;
                    *(uint32_t*)&Ch[a0] = f2bf2(v00, v01);
                    *(uint32_t*)&Ch[a1] = f2bf2(v10, v11);
                }
            } else {
                float2 q0 = *(const float2*)&res[a0];
                float2 q1 = *(const float2*)&res[a1];
                float2 w0, w1;
                w0.x = v00 + q0.x; w0.y = v01 + q0.y;
                w1.x = v10 + q1.x; w1.y = v11 + q1.y;
                *(float2*)&Cf[a0] = w0;
                *(float2*)&Cf[a1] = w1;
            }
        }
    }
}

__global__ __launch_bounds__(256)
void qkv_gemm_kernel(const float* __restrict__ qkv_b)
{
    int b = blockIdx.z;
    gemm_mma<0>(g_wq, qkv_b,
                g_h + (size_t)b * L_ * C_,
                nullptr, nullptr,
                g_qkvh + (size_t)b * M_QKV * L_);
}

__global__ __launch_bounds__(256)
void proj_gemm_kernel(const float* __restrict__ proj_b,
                      const float* __restrict__ x,
                      float* __restrict__ out)
{
    int b = blockIdx.z;
    gemm_mma<1>(g_wp, proj_b,
                g_at + (size_t)b * L_ * C_,
                x   + (size_t)b * C_ * L_,
                out + (size_t)b * C_ * L_,
                nullptr);
}

// ---------------------------------------------------------------------------
// Tensor-core flash attention: 128 threads = 4 warps, warp q-tile 32.
// f16 softmax path, one barrier per k-tile, cp.async K/V double buffer.
// ---------------------------------------------------------------------------
#define QPITCH 136
#define KVPITCH 72
#define AQo 0
#define AKo (64 * QPITCH)
#define AVo (AKo + 2 * 64 * KVPITCH)
#define APo (AVo + 2 * 64 * KVPITCH)
#define ATT_BF16 (APo + 128 * KVPITCH)
#define ATT_BYTES (ATT_BF16 * 2)

__global__ __launch_bounds__(128, 2)
void attn_kernel()
{
    int bh = blockIdx.y;
    int b = bh >> 3, h = bh & 7;
    int l0 = blockIdx.x * 128;

    const uint16_t* Qp = g_qkvh + ((size_t)b * M_QKV + 0 * C_ + h * HD_) * L_;
    const uint16_t* Kp = g_qkvh + ((size_t)b * M_QKV + 1 * C_ + h * HD_) * L_;
    const uint16_t* Vp = g_qkvh + ((size_t)b * M_QKV + 2 * C_ + h * HD_) * L_;

    extern __shared__ uint16_t smh[];
    uint32_t smb = smem_u32(smh);
    uint16_t* Ps = smh + APo;
    uint32_t QsB = smb + AQo * 2, KsB = smb + AKo * 2;
    uint32_t VsB = smb + AVo * 2, PsB = smb + APo * 2;

    int tid  = threadIdx.x;
    int lane = tid & 31, wp = tid >> 5;
    int g = lane >> 2, t4 = lane & 3;
    int qb = wp * 32;
    int l15 = lane & 15;
    int khal = (lane >> 4) * 16;

    const uint32_t ONES_H2 = 0x3C003C00u;

    int a_row = (lane & 7) + ((lane >> 4) << 3);
    int a_col = ((lane >> 3) & 1) * 16;
    int b_row = (lane & 7) + (((lane >> 3) & 1) << 3);
    int b_col = (lane >> 4) * 16;

    auto load_Q = [&]() {
#pragma unroll
        for (int t = 0; t < 8; t++) {
            int idx = tid + t * 128;
            int d = idx >> 4, c = idx & 15;
            CP16(QsB + d * (QPITCH*2) + c * 16, &Qp[(size_t)d * L_ + l0 + c * 8]);
        }
    };
    auto load_K = [&](int k0, int buf) {
        uint32_t base = KsB + buf * 64 * KVPITCH * 2;
#pragma unroll
        for (int t = 0; t < 4; t++) {
            int idx = tid + t * 128;
            int d = idx >> 3, c = idx & 7;
            CP16(base + d * (KVPITCH*2) + c * 16, &Kp[(size_t)d * L_ + k0 + c * 8]);
        }
    };
    auto load_V = [&](int k0, int buf) {
        uint32_t base = VsB + buf * 64 * KVPITCH * 2;
#pragma unroll
        for (int t = 0; t < 4; t++) {
            int idx = tid + t * 128;
            int d = idx >> 3, c = idx & 7;
            CP16(base + d * (KVPITCH*2) + c * 16, &Vp[(size_t)d * L_ + k0 + c * 8]);
        }
    };

    load_Q();
    load_K(0, 0);
    load_V(0, 0);
    CP_COMMIT();
    CP_WAIT0();
    __syncthreads();

    float oacc[2][8][4];
#pragma unroll
    for (int qm = 0; qm < 2; qm++)
#pragma unroll
        for (int nt = 0; nt < 8; nt++)
#pragma unroll
            for (int r = 0; r < 4; r++) oacc[qm][nt][r] = 0.f;
    float sumacc[2][4] = {{0.f,0.f,0.f,0.f},{0.f,0.f,0.f,0.f}};

    for (int kt = 0; kt < 16; kt++) {
        int cur = kt & 1;
        if (kt < 15) {
            load_K((kt + 1) * 64, cur ^ 1);
            load_V((kt + 1) * 64, cur ^ 1);
            CP_COMMIT();
        }
        uint32_t KbB = KsB + cur * 64 * KVPITCH * 2;
        uint32_t VbB = VsB + cur * 64 * KVPITCH * 2;

        float sacc[2][8][4];
#pragma unroll
        for (int qm = 0; qm < 2; qm++)
#pragma unroll
            for (int nt = 0; nt < 8; nt++)
#pragma unroll
                for (int r = 0; r < 4; r++) sacc[qm][nt][r] = 0.f;
#pragma unroll
        for (int kc = 0; kc < 4; kc++) {
            uint32_t af[2][4];
#pragma unroll
            for (int qm = 0; qm < 2; qm++)
                ldsm_x4_t(af[qm], QsB + (kc * 16 + a_row) * (QPITCH*2)
                                 + (qb + qm * 16) * 2 + a_col);
#pragma unroll
            for (int ng = 0; ng < 4; ng++) {
                uint32_t rr[4];
                ldsm_x4_t(rr, KbB + (kc * 16 + b_row) * (KVPITCH*2) + ng * 32 + b_col);
#pragma unroll
                for (int qm = 0; qm < 2; qm++) {
                    mma_bf16(sacc[qm][2*ng],   af[qm], rr[0], rr[1]);
                    mma_bf16(sacc[qm][2*ng+1], af[qm], rr[2], rr[3]);
                }
            }
        }

#pragma unroll
        for (int qm = 0; qm < 2; qm++)
#pragma unroll
            for (int nt = 0; nt < 8; nt++) {
                uint32_t p01 = ex2h2(f2h2(sacc[qm][nt][0], sacc[qm][nt][1]));
                uint32_t p23 = ex2h2(f2h2(sacc[qm][nt][2], sacc[qm][nt][3]));
                *(uint32_t*)&Ps[(qb + qm*16 + g)     * KVPITCH + nt*8 + 2*t4] = p01;
                *(uint32_t*)&Ps[(qb + qm*16 + g + 8) * KVPITCH + nt*8 + 2*t4] = p23;
            }
        __syncwarp();

#pragma unroll
        for (int kc = 0; kc < 4; kc++) {
            int kb = kc * 32 + khal;
            uint32_t af[2][4];
#pragma unroll
            for (int qm = 0; qm < 2; qm++)
                ldsm_x4(af[qm], PsB + (qb + qm*16 + l15) * (KVPITCH*2) + kb);
#pragma unroll
            for (int ng = 0; ng < 4; ng++) {
                uint32_t rr[4];
                ldsm_x4(rr, VbB + (ng * 16 + l15) * (KVPITCH*2) + kb);
#pragma unroll
                for (int qm = 0; qm < 2; qm++) {
                    mma_f16(oacc[qm][2*ng],   af[qm], rr[0], rr[2]);
                    mma_f16(oacc[qm][2*ng+1], af[qm], rr[1], rr[3]);
                }
            }
#pragma unroll
            for (int qm = 0; qm < 2; qm++)
                mma_f16(sumacc[qm], af[qm], ONES_H2, ONES_H2);
        }
        CP_WAIT0();
        __syncthreads();
    }

#pragma unroll
    for (int qm = 0; qm < 2; qm++) {
        float inv0 = 1.f / sumacc[qm][0];
        float inv1 = 1.f / sumacc[qm][2];
        size_t row0 = ((size_t)b * L_ + l0 + qb + qm*16 + g)     * C_ + h * HD_;
        size_t row1 = ((size_t)b * L_ + l0 + qb + qm*16 + g + 8) * C_ + h * HD_;
#pragma unroll
        for (int nt = 0; nt < 8; nt++) {
            int c = nt * 8 + 2 * t4;
            *(uint32_t*)&g_at[row0 + c] = f2bf2(oacc[qm][nt][0] * inv0,
                                                oacc[qm][nt][1] * inv0);
            *(uint32_t*)&g_at[row1 + c] = f2bf2(oacc[qm][nt][2] * inv1,
                                                oacc[qm][nt][3] * inv1);
        }
    }
}

// ---------------------------------------------------------------------------
extern "C" void kernel_launch(void* const* d_in, const int* in_sizes, int n_in,
                              void* d_out, int out_size)
{
    const float* x      = (const float*)d_in[0];
    const float* norm_w = (const float*)d_in[1];
    const float* norm_b = (const float*)d_in[2];
    const float* qkv_w  = (const float*)d_in[3];
    const float* qkv_b  = (const float*)d_in[4];
    const float* proj_w = (const float*)d_in[5];
    const float* proj_b = (const float*)d_in[6];
    float* out = (float*)d_out;

    cudaFuncSetAttribute(attn_kernel,
                         cudaFuncAttributeMaxDynamicSharedMemorySize, ATT_BYTES);
    cudaFuncSetAttribute(qkv_gemm_kernel,
                         cudaFuncAttributeMaxDynamicSharedMemorySize, GSMEM_BYTES);
    cudaFuncSetAttribute(proj_gemm_kernel,
                         cudaFuncAttributeMaxDynamicSharedMemorySize, GSMEM_BYTES);
    cudaFuncSetAttribute(gn_kernel,
                         cudaFuncAttributeMaxDynamicSharedMemorySize, GN_SMEM);

    gn_kernel<<<1536, 256, GN_SMEM>>>(x, norm_w, norm_b, qkv_w, proj_w);

    {
        dim3 grid(L_ / 128, M_QKV / 128, B_);
        qkv_gemm_kernel<<<grid, 256, GSMEM_BYTES>>>(qkv_b);
    }
    {
        dim3 grid(L_ / 128, B_ * NH_);
        attn_kernel<<<grid, 128, ATT_BYTES>>>();
    }
    {
        dim3 grid(L_ / 128, C_ / 128, B_);
        proj_gemm_kernel<<<grid, 256, GSMEM_BYTES>>>(proj_b, x, out);
    }
}

// round 16
// speedup vs baseline: 1.0529x; 1.0529x over previous
#include <cuda_runtime.h>
#include <math.h>
#include <stdint.h>

#define B_   16
#define C_   512
#define L_   1024
#define NH_  8
#define HD_  64
#define NG_  32
#define GCH_ 16
#define M_QKV 1536
#define EPS_ 1e-5f
#define SCQ  0.1803368801111204f   // 0.125 * log2(e)

// Scratch (device globals)
__device__ uint16_t g_h   [(size_t)B_ * L_ * C_];     // groupnorm out bf16 [B][L][C]
__device__ uint16_t g_qkvh[(size_t)B_ * M_QKV * L_];  // qkv [B][3C][L]: Q,K bf16 / V f16
__device__ uint16_t g_at  [(size_t)B_ * L_ * C_];     // attention out bf16 [B][L][C]
__device__ uint16_t g_wq  [(size_t)M_QKV * C_];       // qkv_w bf16
__device__ uint16_t g_wp  [(size_t)C_ * C_];          // proj_w bf16

__device__ __forceinline__ uint32_t smem_u32(const void* p){
    uint32_t a;
    asm("{ .reg .u64 t; cvta.to.shared.u64 t, %1; cvt.u32.u64 %0, t; }" : "=r"(a) : "l"(p));
    return a;
}
__device__ __forceinline__ uint32_t f2bf2(float lo, float hi){
    uint32_t r; asm("cvt.rn.bf16x2.f32 %0, %1, %2;" : "=r"(r) : "f"(hi), "f"(lo)); return r;
}
__device__ __forceinline__ uint32_t f2h2(float lo, float hi){
    uint32_t r; asm("cvt.rn.f16x2.f32 %0, %1, %2;" : "=r"(r) : "f"(hi), "f"(lo)); return r;
}
__device__ __forceinline__ uint32_t ex2h2(uint32_t x){
    uint32_t r; asm("ex2.approx.f16x2 %0, %1;" : "=r"(r) : "r"(x)); return r;
}
__device__ __forceinline__ void ldsm_x4(uint32_t* r, uint32_t addr){
    asm volatile("ldmatrix.sync.aligned.m8n8.x4.shared.b16 {%0,%1,%2,%3}, [%4];"
        : "=r"(r[0]), "=r"(r[1]), "=r"(r[2]), "=r"(r[3]) : "r"(addr));
}
__device__ __forceinline__ void ldsm_x4_t(uint32_t* r, uint32_t addr){
    asm volatile("ldmatrix.sync.aligned.m8n8.x4.trans.shared.b16 {%0,%1,%2,%3}, [%4];"
        : "=r"(r[0]), "=r"(r[1]), "=r"(r[2]), "=r"(r[3]) : "r"(addr));
}
__device__ __forceinline__ void mma_bf16(float* d, const uint32_t* a,
                                         uint32_t b0, uint32_t b1){
    asm volatile(
        "mma.sync.aligned.m16n8k16.row.col.f32.bf16.bf16.f32 "
        "{%0,%1,%2,%3}, {%4,%5,%6,%7}, {%8,%9}, {%0,%1,%2,%3};"
        : "+f"(d[0]), "+f"(d[1]), "+f"(d[2]), "+f"(d[3])
        : "r"(a[0]), "r"(a[1]), "r"(a[2]), "r"(a[3]), "r"(b0), "r"(b1));
}
__device__ __forceinline__ void mma_f16(float* d, const uint32_t* a,
                                        uint32_t b0, uint32_t b1){
    asm volatile(
        "mma.sync.aligned.m16n8k16.row.col.f32.f16.f16.f32 "
        "{%0,%1,%2,%3}, {%4,%5,%6,%7}, {%8,%9}, {%0,%1,%2,%3};"
        : "+f"(d[0]), "+f"(d[1]), "+f"(d[2]), "+f"(d[3])
        : "r"(a[0]), "r"(a[1]), "r"(a[2]), "r"(a[3]), "r"(b0), "r"(b1));
}
#define CP16(dst, src) \
    asm volatile("cp.async.cg.shared.global [%0], [%1], 16;" :: "r"(dst), "l"(src))
#define CP_COMMIT() asm volatile("cp.async.commit_group;" ::: "memory")
#define CP_WAIT0()  asm volatile("cp.async.wait_group 0;" ::: "memory")

// ---------------------------------------------------------------------------
// Fused GroupNorm (single global pass, smem-cached) + weight conversion.
// ---------------------------------------------------------------------------
#define N4Q (M_QKV * C_ / 4)
#define N4P (C_ * C_ / 4)
#define GNP 257
#define GN_SMEM (16 * GNP * 16)

__global__ void gn_kernel(const float* __restrict__ x,
                          const float* __restrict__ w,
                          const float* __restrict__ bn,
                          const float* __restrict__ qkv_w,
                          const float* __restrict__ proj_w)
{
    int tid = threadIdx.x;
    if (blockIdx.x >= 512) {
        int i = (blockIdx.x - 512) * 256 + tid;
        const float4* src;
        uint2* dst;
        if (i < N4Q) { src = (const float4*)qkv_w + i;        dst = (uint2*)g_wq + i; }
        else         { src = (const float4*)proj_w + (i-N4Q); dst = (uint2*)g_wp + (i-N4Q); }
        float4 v = *src;
        uint2 o;
        o.x = f2bf2(v.x, v.y);
        o.y = f2bf2(v.z, v.w);
        *dst = o;
        return;
    }

    extern __shared__ float xs[];
    float4* xs4 = (float4*)xs;

    int gb  = blockIdx.x;
    int b   = gb >> 5;
    int grp = gb & 31;
    const float4* xp4 = (const float4*)(x + ((size_t)b * C_ + (size_t)grp * GCH_) * L_);

    float s = 0.f, s2 = 0.f;
#pragma unroll 4
    for (int i = tid; i < 4096; i += 256) {
        float4 v = xp4[i];
        xs4[(i >> 8) * GNP + (i & 255)] = v;
        s  += v.x + v.y + v.z + v.w;
        s2 += v.x*v.x + v.y*v.y + v.z*v.z + v.w*v.w;
    }
    __shared__ float sh[512];
    sh[tid] = s; sh[256 + tid] = s2;
    __syncthreads();
    for (int off = 128; off > 0; off >>= 1) {
        if (tid < off) { sh[tid] += sh[tid + off]; sh[256 + tid] += sh[256 + tid + off]; }
        __syncthreads();
    }
    __shared__ float sA[16], sB[16];
    if (tid == 0) {
        float mean = sh[0] * (1.f / (GCH_ * L_));
        float var  = sh[256] * (1.f / (GCH_ * L_)) - mean * mean;
        sh[0] = mean;
        sh[1] = rsqrtf(var + EPS_);
    }
    __syncthreads();
    if (tid < 16) {
        float mean = sh[0], inv = sh[1];
        float wc = w[grp * GCH_ + tid], bc = bn[grp * GCH_ + tid];
        sA[tid] = inv * wc;
        sB[tid] = bc - mean * inv * wc;
    }
    __syncthreads();

#pragma unroll
    for (int t = 0; t < 16; t++) {
        int idx = tid + t * 256;
        int l = idx >> 2, cq = idx & 3;
        int c0 = cq * 4;
        float v0 = xs[(c0+0) * (GNP*4) + l] * sA[c0+0] + sB[c0+0];
        float v1 = xs[(c0+1) * (GNP*4) + l] * sA[c0+1] + sB[c0+1];
        float v2 = xs[(c0+2) * (GNP*4) + l] * sA[c0+2] + sB[c0+2];
        float v3 = xs[(c0+3) * (GNP*4) + l] * sA[c0+3] + sB[c0+3];
        uint2 o;
        o.x = f2bf2(v0, v1);
        o.y = f2bf2(v2, v3);
        *(uint2*)&g_h[((size_t)b * L_ + l) * C_ + grp * GCH_ + c0] = o;
    }
}

// ---------------------------------------------------------------------------
// bf16 GEMM (R13 config): BK=64, 2-stage cp.async, 256 threads (2m x 4n).
// MODE 0 (qkv): region stores — Q scaled bf16 / K bf16 / V f16.
// MODE 1 (proj): fp32 + residual.
// ---------------------------------------------------------------------------
#define GP 72
#define GSTG (128 * GP)
#define STAGE_B (2 * GSTG * 2)
#define GSMEM_BYTES (2 * STAGE_B)

template <int MODE>
__device__ __forceinline__ void gemm_mma(const uint16_t* __restrict__ Aw,
                                         const float* __restrict__ bias,
                                         const uint16_t* __restrict__ Bg,
                                         const float* __restrict__ res,
                                         float* __restrict__ Cf,
                                         uint16_t* __restrict__ Ch)
{
    extern __shared__ uint16_t smh[];
    uint32_t smb = smem_u32(smh);
    int tid  = threadIdx.x;
    int wid  = tid >> 5, lane = tid & 31;
    int g    = lane >> 2, t4 = lane & 3;
    int wm   = wid & 1;
    int wn   = wid >> 1;
    int o0   = blockIdx.y * 128;
    int l0   = blockIdx.x * 128;
    int mb   = wm * 64;
    int nb   = wn * 32;
    int l15  = lane & 15;
    int khal = (lane >> 4) * 16;

    float acc[4][4][4];
#pragma unroll
    for (int mt = 0; mt < 4; mt++)
#pragma unroll
        for (int nt = 0; nt < 4; nt++)
#pragma unroll
            for (int r = 0; r < 4; r++) acc[mt][nt][r] = 0.f;

    auto issue = [&](int st, int c0) {
        uint32_t base = smb + st * STAGE_B;
#pragma unroll
        for (int t = 0; t < 4; t++) {
            int idx = tid + t * 256;
            int row = idx >> 3, c = idx & 7;
            CP16(base + row * 144 + c * 16,
                 &Aw[(size_t)(o0 + row) * C_ + c0 + c * 8]);
            CP16(base + GSTG * 2 + row * 144 + c * 16,
                 &Bg[(size_t)(l0 + row) * C_ + c0 + c * 8]);
        }
    };

    issue(0, 0);  CP_COMMIT();

    for (int it = 0; it < 8; ++it) {
        CP_WAIT0();
        __syncthreads();
        if (it < 7) { issue((it + 1) & 1, (it + 1) * 64); CP_COMMIT(); }

        uint32_t AsB = smb + (it & 1) * STAGE_B;
        uint32_t BsB = AsB + GSTG * 2;
#pragma unroll
        for (int ks = 0; ks < 4; ks++) {
            int kb = ks * 32 + khal;
            uint32_t af[4][4];
#pragma unroll
            for (int mt = 0; mt < 4; mt++)
                ldsm_x4(af[mt], AsB + (mb + mt * 16 + l15) * 144 + kb);
            uint32_t bf[4][2];
#pragma unroll
            for (int ng = 0; ng < 2; ng++) {
                uint32_t rr[4];
                ldsm_x4(rr, BsB + (nb + ng * 16 + l15) * 144 + kb);
                bf[2*ng][0]   = rr[0]; bf[2*ng][1]   = rr[2];
                bf[2*ng+1][0] = rr[1]; bf[2*ng+1][1] = rr[3];
            }
#pragma unroll
            for (int mt = 0; mt < 4; mt++)
#pragma unroll
                for (int nt = 0; nt < 4; nt++)
                    mma_bf16(acc[mt][nt], af[mt], bf[nt][0], bf[nt][1]);
        }
    }

    int region = o0 >> 9;     // qkv: 0=Q, 1=K, 2=V
    float qscale = (MODE == 0 && region == 0) ? SCQ : 1.f;

#pragma unroll
    for (int mt = 0; mt < 4; mt++) {
        int r0 = o0 + mb + mt * 16 + g;
        int r1 = r0 + 8;
        float bv0 = bias[r0], bv1 = bias[r1];
#pragma unroll
        for (int nt = 0; nt < 4; nt++) {
            int col = l0 + nb + nt * 8 + 2 * t4;
            size_t a0 = (size_t)r0 * L_ + col;
            size_t a1 = (size_t)r1 * L_ + col;
            float v00 = acc[mt][nt][0] + bv0, v01 = acc[mt][nt][1] + bv0;
            float v10 = acc[mt][nt][2] + bv1, v11 = acc[mt][nt][3] + bv1;
            if (MODE == 0) {
                if (region == 2) {
                    *(uint32_t*)&Ch[a0] = f2h2(v00, v01);
                    *(uint32_t*)&Ch[a1] = f2h2(v10, v11);
                } else {
                    v00 *= qscale; v01 *= qscale; v10 *= qscale; v11 *= qscale;
                    *(uint32_t*)&Ch[a0] = f2bf2(v00, v01);
                    *(uint32_t*)&Ch[a1] = f2bf2(v10, v11);
                }
            } else {
                float2 q0 = *(const float2*)&res[a0];
                float2 q1 = *(const float2*)&res[a1];
                float2 w0, w1;
                w0.x = v00 + q0.x; w0.y = v01 + q0.y;
                w1.x = v10 + q1.x; w1.y = v11 + q1.y;
                *(float2*)&Cf[a0] = w0;
                *(float2*)&Cf[a1] = w1;
            }
        }
    }
}

__global__ __launch_bounds__(256)
void qkv_gemm_kernel(const float* __restrict__ qkv_b)
{
    int b = blockIdx.z;
    gemm_mma<0>(g_wq, qkv_b,
                g_h + (size_t)b * L_ * C_,
                nullptr, nullptr,
                g_qkvh + (size_t)b * M_QKV * L_);
}

__global__ __launch_bounds__(256)
void proj_gemm_kernel(const float* __restrict__ proj_b,
                      const float* __restrict__ x,
                      float* __restrict__ out)
{
    int b = blockIdx.z;
    gemm_mma<1>(g_wp, proj_b,
                g_at + (size_t)b * L_ * C_,
                x   + (size_t)b * C_ * L_,
                out + (size_t)b * C_ * L_,
                nullptr);
}

// ---------------------------------------------------------------------------
// Tensor-core flash attention: 128 threads = 4 warps, warp q-tile 32.
// P is REGISTER-RESIDENT: the exp'd f16x2 S fragments are reused directly as
// the PV A-operand (identical lane layout) — no smem round trip for P.
// ---------------------------------------------------------------------------
#define QPITCH 136
#define KVPITCH 72
#define AQo 0
#define AKo (64 * QPITCH)
#define AVo (AKo + 2 * 64 * KVPITCH)
#define ATT_BF16 (AVo + 2 * 64 * KVPITCH)
#define ATT_BYTES (ATT_BF16 * 2)

__global__ __launch_bounds__(128, 2)
void attn_kernel()
{
    int bh = blockIdx.y;
    int b = bh >> 3, h = bh & 7;
    int l0 = blockIdx.x * 128;

    const uint16_t* Qp = g_qkvh + ((size_t)b * M_QKV + 0 * C_ + h * HD_) * L_;
    const uint16_t* Kp = g_qkvh + ((size_t)b * M_QKV + 1 * C_ + h * HD_) * L_;
    const uint16_t* Vp = g_qkvh + ((size_t)b * M_QKV + 2 * C_ + h * HD_) * L_;

    extern __shared__ uint16_t smh[];
    uint32_t smb = smem_u32(smh);
    uint32_t QsB = smb + AQo * 2, KsB = smb + AKo * 2;
    uint32_t VsB = smb + AVo * 2;

    int tid  = threadIdx.x;
    int lane = tid & 31, wp = tid >> 5;
    int g = lane >> 2, t4 = lane & 3;
    int qb = wp * 32;
    int l15 = lane & 15;
    int khal = (lane >> 4) * 16;

    const uint32_t ONES_H2 = 0x3C003C00u;

    int a_row = (lane & 7) + ((lane >> 4) << 3);
    int a_col = ((lane >> 3) & 1) * 16;
    int b_row = (lane & 7) + (((lane >> 3) & 1) << 3);
    int b_col = (lane >> 4) * 16;

    auto load_Q = [&]() {
#pragma unroll
        for (int t = 0; t < 8; t++) {
            int idx = tid + t * 128;
            int d = idx >> 4, c = idx & 15;
            CP16(QsB + d * (QPITCH*2) + c * 16, &Qp[(size_t)d * L_ + l0 + c * 8]);
        }
    };
    auto load_K = [&](int k0, int buf) {
        uint32_t base = KsB + buf * 64 * KVPITCH * 2;
#pragma unroll
        for (int t = 0; t < 4; t++) {
            int idx = tid + t * 128;
            int d = idx >> 3, c = idx & 7;
            CP16(base + d * (KVPITCH*2) + c * 16, &Kp[(size_t)d * L_ + k0 + c * 8]);
        }
    };
    auto load_V = [&](int k0, int buf) {
        uint32_t base = VsB + buf * 64 * KVPITCH * 2;
#pragma unroll
        for (int t = 0; t < 4; t++) {
            int idx = tid + t * 128;
            int d = idx >> 3, c = idx & 7;
            CP16(base + d * (KVPITCH*2) + c * 16, &Vp[(size_t)d * L_ + k0 + c * 8]);
        }
    };

    load_Q();
    load_K(0, 0);
    load_V(0, 0);
    CP_COMMIT();
    CP_WAIT0();
    __syncthreads();

    float oacc[2][8][4];
#pragma unroll
    for (int qm = 0; qm < 2; qm++)
#pragma unroll
        for (int nt = 0; nt < 8; nt++)
#pragma unroll
            for (int r = 0; r < 4; r++) oacc[qm][nt][r] = 0.f;
    float sumacc[2][4] = {{0.f,0.f,0.f,0.f},{0.f,0.f,0.f,0.f}};

    for (int kt = 0; kt < 16; kt++) {
        int cur = kt & 1;
        if (kt < 15) {
            load_K((kt + 1) * 64, cur ^ 1);
            load_V((kt + 1) * 64, cur ^ 1);
            CP_COMMIT();
        }
        uint32_t KbB = KsB + cur * 64 * KVPITCH * 2;
        uint32_t VbB = VsB + cur * 64 * KVPITCH * 2;

        // S = Q K^T
        float sacc[2][8][4];
#pragma unroll
        for (int qm = 0; qm < 2; qm++)
#pragma unroll
            for (int nt = 0; nt < 8; nt++)
#pragma unroll
                for (int r = 0; r < 4; r++) sacc[qm][nt][r] = 0.f;
#pragma unroll
        for (int kc = 0; kc < 4; kc++) {
            uint32_t af[2][4];
#pragma unroll
            for (int qm = 0; qm < 2; qm++)
                ldsm_x4_t(af[qm], QsB + (kc * 16 + a_row) * (QPITCH*2)
                                 + (qb + qm * 16) * 2 + a_col);
#pragma unroll
            for (int ng = 0; ng < 4; ng++) {
                uint32_t rr[4];
                ldsm_x4_t(rr, KbB + (kc * 16 + b_row) * (KVPITCH*2) + ng * 32 + b_col);
#pragma unroll
                for (int qm = 0; qm < 2; qm++) {
                    mma_bf16(sacc[qm][2*ng],   af[qm], rr[0], rr[1]);
                    mma_bf16(sacc[qm][2*ng+1], af[qm], rr[2], rr[3]);
                }
            }
        }

        // P = exp2(S) in f16x2 — kept in registers.
        // p01[qm][nt] = rows (qb+qm*16+g), cols nt*8+2t4..+1
        // p23[qm][nt] = rows (qb+qm*16+g+8), same cols
        uint32_t p01[2][8], p23[2][8];
#pragma unroll
        for (int qm = 0; qm < 2; qm++)
#pragma unroll
            for (int nt = 0; nt < 8; nt++) {
                p01[qm][nt] = ex2h2(f2h2(sacc[qm][nt][0], sacc[qm][nt][1]));
                p23[qm][nt] = ex2h2(f2h2(sacc[qm][nt][2], sacc[qm][nt][3]));
            }

        // O += P V  and  rsum += P*ones; A-fragment built directly from p-regs:
        // af = { p01[2kc], p23[2kc], p01[2kc+1], p23[2kc+1] }
#pragma unroll
        for (int kc = 0; kc < 4; kc++) {
            int kb = kc * 32 + khal;
            uint32_t af[2][4];
#pragma unroll
            for (int qm = 0; qm < 2; qm++) {
                af[qm][0] = p01[qm][2*kc];
                af[qm][1] = p23[qm][2*kc];
                af[qm][2] = p01[qm][2*kc+1];
                af[qm][3] = p23[qm][2*kc+1];
            }
#pragma unroll
            for (int ng = 0; ng < 4; ng++) {
                uint32_t rr[4];
                ldsm_x4(rr, VbB + (ng * 16 + l15) * (KVPITCH*2) + kb);
#pragma unroll
                for (int qm = 0; qm < 2; qm++) {
                    mma_f16(oacc[qm][2*ng],   af[qm], rr[0], rr[2]);
                    mma_f16(oacc[qm][2*ng+1], af[qm], rr[1], rr[3]);
                }
            }
#pragma unroll
            for (int qm = 0; qm < 2; qm++)
                mma_f16(sumacc[qm], af[qm], ONES_H2, ONES_H2);
        }
        CP_WAIT0();
        __syncthreads();
    }

#pragma unroll
    for (int qm = 0; qm < 2; qm++) {
        float inv0 = 1.f / sumacc[qm][0];
        float inv1 = 1.f / sumacc[qm][2];
        size_t row0 = ((size_t)b * L_ + l0 + qb + qm*16 + g)     * C_ + h * HD_;
        size_t row1 = ((size_t)b * L_ + l0 + qb + qm*16 + g + 8) * C_ + h * HD_;
#pragma unroll
        for (int nt = 0; nt < 8; nt++) {
            int c = nt * 8 + 2 * t4;
            *(uint32_t*)&g_at[row0 + c] = f2bf2(oacc[qm][nt][0] * inv0,
                                                oacc[qm][nt][1] * inv0);
            *(uint32_t*)&g_at[row1 + c] = f2bf2(oacc[qm][nt][2] * inv1,
                                                oacc[qm][nt][3] * inv1);
        }
    }
}

// ---------------------------------------------------------------------------
extern "C" void kernel_launch(void* const* d_in, const int* in_sizes, int n_in,
                              void* d_out, int out_size)
{
    const float* x      = (const float*)d_in[0];
    const float* norm_w = (const float*)d_in[1];
    const float* norm_b = (const float*)d_in[2];
    const float* qkv_w  = (const float*)d_in[3];
    const float* qkv_b  = (const float*)d_in[4];
    const float* proj_w = (const float*)d_in[5];
    const float* proj_b = (const float*)d_in[6];
    float* out = (float*)d_out;

    cudaFuncSetAttribute(attn_kernel,
                         cudaFuncAttributeMaxDynamicSharedMemorySize, ATT_BYTES);
    cudaFuncSetAttribute(qkv_gemm_kernel,
                         cudaFuncAttributeMaxDynamicSharedMemorySize, GSMEM_BYTES);
    cudaFuncSetAttribute(proj_gemm_kernel,
                         cudaFuncAttributeMaxDynamicSharedMemorySize, GSMEM_BYTES);
    cudaFuncSetAttribute(gn_kernel,
                         cudaFuncAttributeMaxDynamicSharedMemorySize, GN_SMEM);

    gn_kernel<<<1536, 256, GN_SMEM>>>(x, norm_w, norm_b, qkv_w, proj_w);

    {
        dim3 grid(L_ / 128, M_QKV / 128, B_);
        qkv_gemm_kernel<<<grid, 256, GSMEM_BYTES>>>(qkv_b);
    }
    {
        dim3 grid(L_ / 128, B_ * NH_);
        attn_kernel<<<grid, 128, ATT_BYTES>>>();
    }
    {
        dim3 grid(L_ / 128, C_ / 128, B_);
        proj_gemm_kernel<<<grid, 256, GSMEM_BYTES>>>(proj_b, x, out);
    }
}

// round 17
// speedup vs baseline: 1.0672x; 1.0136x over previous
#include <cuda_runtime.h>
#include <math.h>
#include <stdint.h>

#define B_   16
#define C_   512
#define L_   1024
#define NH_  8
#define HD_  64
#define NG_  32
#define GCH_ 16
#define M_QKV 1536
#define EPS_ 1e-5f
#define SCQ  0.1803368801111204f   // 0.125 * log2(e)

// Scratch (device globals)
__device__ uint16_t g_h   [(size_t)B_ * L_ * C_];     // groupnorm out bf16 [B][L][C]
__device__ uint16_t g_qkvh[(size_t)B_ * M_QKV * L_];  // qkv [B][3C][L]: Q,K bf16 / V f16
__device__ uint16_t g_at  [(size_t)B_ * L_ * C_];     // attention out bf16 [B][L][C]
__device__ uint16_t g_wq  [(size_t)M_QKV * C_];       // qkv_w bf16
__device__ uint16_t g_wp  [(size_t)C_ * C_];          // proj_w bf16

__device__ __forceinline__ uint32_t smem_u32(const void* p){
    uint32_t a;
    asm("{ .reg .u64 t; cvta.to.shared.u64 t, %1; cvt.u32.u64 %0, t; }" : "=r"(a) : "l"(p));
    return a;
}
__device__ __forceinline__ uint32_t f2bf2(float lo, float hi){
    uint32_t r; asm("cvt.rn.bf16x2.f32 %0, %1, %2;" : "=r"(r) : "f"(hi), "f"(lo)); return r;
}
__device__ __forceinline__ uint32_t f2h2(float lo, float hi){
    uint32_t r; asm("cvt.rn.f16x2.f32 %0, %1, %2;" : "=r"(r) : "f"(hi), "f"(lo)); return r;
}
__device__ __forceinline__ uint32_t ex2h2(uint32_t x){
    uint32_t r; asm("ex2.approx.f16x2 %0, %1;" : "=r"(r) : "r"(x)); return r;
}
__device__ __forceinline__ void ldsm_x4(uint32_t* r, uint32_t addr){
    asm volatile("ldmatrix.sync.aligned.m8n8.x4.shared.b16 {%0,%1,%2,%3}, [%4];"
        : "=r"(r[0]), "=r"(r[1]), "=r"(r[2]), "=r"(r[3]) : "r"(addr));
}
__device__ __forceinline__ void ldsm_x4_t(uint32_t* r, uint32_t addr){
    asm volatile("ldmatrix.sync.aligned.m8n8.x4.trans.shared.b16 {%0,%1,%2,%3}, [%4];"
        : "=r"(r[0]), "=r"(r[1]), "=r"(r[2]), "=r"(r[3]) : "r"(addr));
}
__device__ __forceinline__ void mma_bf16(float* d, const uint32_t* a,
                                         uint32_t b0, uint32_t b1){
    asm volatile(
        "mma.sync.aligned.m16n8k16.row.col.f32.bf16.bf16.f32 "
        "{%0,%1,%2,%3}, {%4,%5,%6,%7}, {%8,%9}, {%0,%1,%2,%3};"
        : "+f"(d[0]), "+f"(d[1]), "+f"(d[2]), "+f"(d[3])
        : "r"(a[0]), "r"(a[1]), "r"(a[2]), "r"(a[3]), "r"(b0), "r"(b1));
}
__device__ __forceinline__ void mma_f16(float* d, const uint32_t* a,
                                        uint32_t b0, uint32_t b1){
    asm volatile(
        "mma.sync.aligned.m16n8k16.row.col.f32.f16.f16.f32 "
        "{%0,%1,%2,%3}, {%4,%5,%6,%7}, {%8,%9}, {%0,%1,%2,%3};"
        : "+f"(d[0]), "+f"(d[1]), "+f"(d[2]), "+f"(d[3])
        : "r"(a[0]), "r"(a[1]), "r"(a[2]), "r"(a[3]), "r"(b0), "r"(b1));
}
#define CP16(dst, src) \
    asm volatile("cp.async.cg.shared.global [%0], [%1], 16;" :: "r"(dst), "l"(src))
#define CP_COMMIT() asm volatile("cp.async.commit_group;" ::: "memory")
#define CP_WAIT0()  asm volatile("cp.async.wait_group 0;" ::: "memory")

// ---------------------------------------------------------------------------
// Fused GroupNorm (single global pass, smem-cached) + weight conversion.
// ---------------------------------------------------------------------------
#define N4Q (M_QKV * C_ / 4)
#define N4P (C_ * C_ / 4)
#define GNP 257
#define GN_SMEM (16 * GNP * 16)

__global__ void gn_kernel(const float* __restrict__ x,
                          const float* __restrict__ w,
                          const float* __restrict__ bn,
                          const float* __restrict__ qkv_w,
                          const float* __restrict__ proj_w)
{
    int tid = threadIdx.x;
    if (blockIdx.x >= 512) {
        int i = (blockIdx.x - 512) * 256 + tid;
        const float4* src;
        uint2* dst;
        if (i < N4Q) { src = (const float4*)qkv_w + i;        dst = (uint2*)g_wq + i; }
        else         { src = (const float4*)proj_w + (i-N4Q); dst = (uint2*)g_wp + (i-N4Q); }
        float4 v = *src;
        uint2 o;
        o.x = f2bf2(v.x, v.y);
        o.y = f2bf2(v.z, v.w);
        *dst = o;
        return;
    }

    extern __shared__ float xs[];
    float4* xs4 = (float4*)xs;

    int gb  = blockIdx.x;
    int b   = gb >> 5;
    int grp = gb & 31;
    const float4* xp4 = (const float4*)(x + ((size_t)b * C_ + (size_t)grp * GCH_) * L_);

    float s = 0.f, s2 = 0.f;
#pragma unroll 4
    for (int i = tid; i < 4096; i += 256) {
        float4 v = xp4[i];
        xs4[(i >> 8) * GNP + (i & 255)] = v;
        s  += v.x + v.y + v.z + v.w;
        s2 += v.x*v.x + v.y*v.y + v.z*v.z + v.w*v.w;
    }
    __shared__ float sh[512];
    sh[tid] = s; sh[256 + tid] = s2;
    __syncthreads();
    for (int off = 128; off > 0; off >>= 1) {
        if (tid < off) { sh[tid] += sh[tid + off]; sh[256 + tid] += sh[256 + tid + off]; }
        __syncthreads();
    }
    __shared__ float sA[16], sB[16];
    if (tid == 0) {
        float mean = sh[0] * (1.f / (GCH_ * L_));
        float var  = sh[256] * (1.f / (GCH_ * L_)) - mean * mean;
        sh[0] = mean;
        sh[1] = rsqrtf(var + EPS_);
    }
    __syncthreads();
    if (tid < 16) {
        float mean = sh[0], inv = sh[1];
        float wc = w[grp * GCH_ + tid], bc = bn[grp * GCH_ + tid];
        sA[tid] = inv * wc;
        sB[tid] = bc - mean * inv * wc;
    }
    __syncthreads();

#pragma unroll
    for (int t = 0; t < 16; t++) {
        int idx = tid + t * 256;
        int l = idx >> 2, cq = idx & 3;
        int c0 = cq * 4;
        float v0 = xs[(c0+0) * (GNP*4) + l] * sA[c0+0] + sB[c0+0];
        float v1 = xs[(c0+1) * (GNP*4) + l] * sA[c0+1] + sB[c0+1];
        float v2 = xs[(c0+2) * (GNP*4) + l] * sA[c0+2] + sB[c0+2];
        float v3 = xs[(c0+3) * (GNP*4) + l] * sA[c0+3] + sB[c0+3];
        uint2 o;
        o.x = f2bf2(v0, v1);
        o.y = f2bf2(v2, v3);
        *(uint2*)&g_h[((size_t)b * L_ + l) * C_ + grp * GCH_ + c0] = o;
    }
}

// ---------------------------------------------------------------------------
// bf16 GEMM (R13 config): BK=64, 2-stage cp.async, 256 threads (2m x 4n).
// MODE 0 (qkv): region stores — Q scaled bf16 / K bf16 / V f16.
// MODE 1 (proj): fp32 + residual.
// ---------------------------------------------------------------------------
#define GP 72
#define GSTG (128 * GP)
#define STAGE_B (2 * GSTG * 2)
#define GSMEM_BYTES (2 * STAGE_B)

template <int MODE>
__device__ __forceinline__ void gemm_mma(const uint16_t* __restrict__ Aw,
                                         const float* __restrict__ bias,
                                         const uint16_t* __restrict__ Bg,
                                         const float* __restrict__ res,
                                         float* __restrict__ Cf,
                                         uint16_t* __restrict__ Ch)
{
    extern __shared__ uint16_t smh[];
    uint32_t smb = smem_u32(smh);
    int tid  = threadIdx.x;
    int wid  = tid >> 5, lane = tid & 31;
    int g    = lane >> 2, t4 = lane & 3;
    int wm   = wid & 1;
    int wn   = wid >> 1;
    int o0   = blockIdx.y * 128;
    int l0   = blockIdx.x * 128;
    int mb   = wm * 64;
    int nb   = wn * 32;
    int l15  = lane & 15;
    int khal = (lane >> 4) * 16;

    float acc[4][4][4];
#pragma unroll
    for (int mt = 0; mt < 4; mt++)
#pragma unroll
        for (int nt = 0; nt < 4; nt++)
#pragma unroll
            for (int r = 0; r < 4; r++) acc[mt][nt][r] = 0.f;

    auto issue = [&](int st, int c0) {
        uint32_t base = smb + st * STAGE_B;
#pragma unroll
        for (int t = 0; t < 4; t++) {
            int idx = tid + t * 256;
            int row = idx >> 3, c = idx & 7;
            CP16(base + row * 144 + c * 16,
                 &Aw[(size_t)(o0 + row) * C_ + c0 + c * 8]);
            CP16(base + GSTG * 2 + row * 144 + c * 16,
                 &Bg[(size_t)(l0 + row) * C_ + c0 + c * 8]);
        }
    };

    issue(0, 0);  CP_COMMIT();

    for (int it = 0; it < 8; ++it) {
        CP_WAIT0();
        __syncthreads();
        if (it < 7) { issue((it + 1) & 1, (it + 1) * 64); CP_COMMIT(); }

        uint32_t AsB = smb + (it & 1) * STAGE_B;
        uint32_t BsB = AsB + GSTG * 2;
#pragma unroll
        for (int ks = 0; ks < 4; ks++) {
            int kb = ks * 32 + khal;
            uint32_t af[4][4];
#pragma unroll
            for (int mt = 0; mt < 4; mt++)
                ldsm_x4(af[mt], AsB + (mb + mt * 16 + l15) * 144 + kb);
            uint32_t bf[4][2];
#pragma unroll
            for (int ng = 0; ng < 2; ng++) {
                uint32_t rr[4];
                ldsm_x4(rr, BsB + (nb + ng * 16 + l15) * 144 + kb);
                bf[2*ng][0]   = rr[0]; bf[2*ng][1]   = rr[2];
                bf[2*ng+1][0] = rr[1]; bf[2*ng+1][1] = rr[3];
            }
#pragma unroll
            for (int mt = 0; mt < 4; mt++)
#pragma unroll
                for (int nt = 0; nt < 4; nt++)
                    mma_bf16(acc[mt][nt], af[mt], bf[nt][0], bf[nt][1]);
        }
    }

    int region = o0 >> 9;     // qkv: 0=Q, 1=K, 2=V
    float qscale = (MODE == 0 && region == 0) ? SCQ : 1.f;

#pragma unroll
    for (int mt = 0; mt < 4; mt++) {
        int r0 = o0 + mb + mt * 16 + g;
        int r1 = r0 + 8;
        float bv0 = bias[r0], bv1 = bias[r1];
#pragma unroll
        for (int nt = 0; nt < 4; nt++) {
            int col = l0 + nb + nt * 8 + 2 * t4;
            size_t a0 = (size_t)r0 * L_ + col;
            size_t a1 = (size_t)r1 * L_ + col;
            float v00 = acc[mt][nt][0] + bv0, v01 = acc[mt][nt][1] + bv0;
            float v10 = acc[mt][nt][2] + bv1, v11 = acc[mt][nt][3] + bv1;
            if (MODE == 0) {
                if (region == 2) {
                    *(uint32_t*)&Ch[a0] = f2h2(v00, v01);
                    *(uint32_t*)&Ch[a1] = f2h2(v10, v11);
                } else {
                    v00 *= qscale; v01 *= qscale; v10 *= qscale; v11 *= qscale;
                    *(uint32_t*)&Ch[a0] = f2bf2(v00, v01);
                    *(uint32_t*)&Ch[a1] = f2bf2(v10, v11);
                }
            } else {
                float2 q0 = *(const float2*)&res[a0];
                float2 q1 = *(const float2*)&res[a1];
                float2 w0, w1;
                w0.x = v00 + q0.x; w0.y = v01 + q0.y;
                w1.x = v10 + q1.x; w1.y = v11 + q1.y;
                *(float2*)&Cf[a0] = w0;
                *(float2*)&Cf[a1] = w1;
            }
        }
    }
}

__global__ __launch_bounds__(256)
void qkv_gemm_kernel(const float* __restrict__ qkv_b)
{
    int b = blockIdx.z;
    gemm_mma<0>(g_wq, qkv_b,
                g_h + (size_t)b * L_ * C_,
                nullptr, nullptr,
                g_qkvh + (size_t)b * M_QKV * L_);
}

__global__ __launch_bounds__(256)
void proj_gemm_kernel(const float* __restrict__ proj_b,
                      const float* __restrict__ x,
                      float* __restrict__ out)
{
    int b = blockIdx.z;
    gemm_mma<1>(g_wp, proj_b,
                g_at + (size_t)b * L_ * C_,
                x   + (size_t)b * C_ * L_,
                out + (size_t)b * C_ * L_,
                nullptr);
}

// ---------------------------------------------------------------------------
// Tensor-core flash attention: 128 threads = 4 warps, warp q-tile 32.
// Q fragments HOISTED into registers (loop-invariant); P register-resident.
// ---------------------------------------------------------------------------
#define QPITCH 136
#define KVPITCH 72
#define AQo 0
#define AKo (64 * QPITCH)
#define AVo (AKo + 2 * 64 * KVPITCH)
#define ATT_BF16 (AVo + 2 * 64 * KVPITCH)
#define ATT_BYTES (ATT_BF16 * 2)

__global__ __launch_bounds__(128, 2)
void attn_kernel()
{
    int bh = blockIdx.y;
    int b = bh >> 3, h = bh & 7;
    int l0 = blockIdx.x * 128;

    const uint16_t* Qp = g_qkvh + ((size_t)b * M_QKV + 0 * C_ + h * HD_) * L_;
    const uint16_t* Kp = g_qkvh + ((size_t)b * M_QKV + 1 * C_ + h * HD_) * L_;
    const uint16_t* Vp = g_qkvh + ((size_t)b * M_QKV + 2 * C_ + h * HD_) * L_;

    extern __shared__ uint16_t smh[];
    uint32_t smb = smem_u32(smh);
    uint32_t QsB = smb + AQo * 2, KsB = smb + AKo * 2;
    uint32_t VsB = smb + AVo * 2;

    int tid  = threadIdx.x;
    int lane = tid & 31, wp = tid >> 5;
    int g = lane >> 2, t4 = lane & 3;
    int qb = wp * 32;
    int l15 = lane & 15;
    int khal = (lane >> 4) * 16;

    const uint32_t ONES_H2 = 0x3C003C00u;

    int a_row = (lane & 7) + ((lane >> 4) << 3);
    int a_col = ((lane >> 3) & 1) * 16;
    int b_row = (lane & 7) + (((lane >> 3) & 1) << 3);
    int b_col = (lane >> 4) * 16;

    auto load_Q = [&]() {
#pragma unroll
        for (int t = 0; t < 8; t++) {
            int idx = tid + t * 128;
            int d = idx >> 4, c = idx & 15;
            CP16(QsB + d * (QPITCH*2) + c * 16, &Qp[(size_t)d * L_ + l0 + c * 8]);
        }
    };
    auto load_K = [&](int k0, int buf) {
        uint32_t base = KsB + buf * 64 * KVPITCH * 2;
#pragma unroll
        for (int t = 0; t < 4; t++) {
            int idx = tid + t * 128;
            int d = idx >> 3, c = idx & 7;
            CP16(base + d * (KVPITCH*2) + c * 16, &Kp[(size_t)d * L_ + k0 + c * 8]);
        }
    };
    auto load_V = [&](int k0, int buf) {
        uint32_t base = VsB + buf * 64 * KVPITCH * 2;
#pragma unroll
        for (int t = 0; t < 4; t++) {
            int idx = tid + t * 128;
            int d = idx >> 3, c = idx & 7;
            CP16(base + d * (KVPITCH*2) + c * 16, &Vp[(size_t)d * L_ + k0 + c * 8]);
        }
    };

    load_Q();
    load_K(0, 0);
    load_V(0, 0);
    CP_COMMIT();
    CP_WAIT0();
    __syncthreads();

    // Hoist Q fragments (loop-invariant): qf[qm][kc][4]
    uint32_t qf[2][4][4];
#pragma unroll
    for (int kc = 0; kc < 4; kc++)
#pragma unroll
        for (int qm = 0; qm < 2; qm++)
            ldsm_x4_t(qf[qm][kc], QsB + (kc * 16 + a_row) * (QPITCH*2)
                                  + (qb + qm * 16) * 2 + a_col);

    float oacc[2][8][4];
#pragma unroll
    for (int qm = 0; qm < 2; qm++)
#pragma unroll
        for (int nt = 0; nt < 8; nt++)
#pragma unroll
            for (int r = 0; r < 4; r++) oacc[qm][nt][r] = 0.f;
    float sumacc[2][4] = {{0.f,0.f,0.f,0.f},{0.f,0.f,0.f,0.f}};

    for (int kt = 0; kt < 16; kt++) {
        int cur = kt & 1;
        if (kt < 15) {
            load_K((kt + 1) * 64, cur ^ 1);
            load_V((kt + 1) * 64, cur ^ 1);
            CP_COMMIT();
        }
        uint32_t KbB = KsB + cur * 64 * KVPITCH * 2;
        uint32_t VbB = VsB + cur * 64 * KVPITCH * 2;

        // S = Q K^T (Q from registers)
        float sacc[2][8][4];
#pragma unroll
        for (int qm = 0; qm < 2; qm++)
#pragma unroll
            for (int nt = 0; nt < 8; nt++)
#pragma unroll
                for (int r = 0; r < 4; r++) sacc[qm][nt][r] = 0.f;
#pragma unroll
        for (int kc = 0; kc < 4; kc++) {
#pragma unroll
            for (int ng = 0; ng < 4; ng++) {
                uint32_t rr[4];
                ldsm_x4_t(rr, KbB + (kc * 16 + b_row) * (KVPITCH*2) + ng * 32 + b_col);
#pragma unroll
                for (int qm = 0; qm < 2; qm++) {
                    mma_bf16(sacc[qm][2*ng],   qf[qm][kc], rr[0], rr[1]);
                    mma_bf16(sacc[qm][2*ng+1], qf[qm][kc], rr[2], rr[3]);
                }
            }
        }

        // P = exp2(S) in f16x2 — register-resident
        uint32_t p01[2][8], p23[2][8];
#pragma unroll
        for (int qm = 0; qm < 2; qm++)
#pragma unroll
            for (int nt = 0; nt < 8; nt++) {
                p01[qm][nt] = ex2h2(f2h2(sacc[qm][nt][0], sacc[qm][nt][1]));
                p23[qm][nt] = ex2h2(f2h2(sacc[qm][nt][2], sacc[qm][nt][3]));
            }

        // O += P V  and  rsum += P*ones (A-fragments straight from p-regs)
#pragma unroll
        for (int kc = 0; kc < 4; kc++) {
            int kb = kc * 32 + khal;
            uint32_t af[2][4];
#pragma unroll
            for (int qm = 0; qm < 2; qm++) {
                af[qm][0] = p01[qm][2*kc];
                af[qm][1] = p23[qm][2*kc];
                af[qm][2] = p01[qm][2*kc+1];
                af[qm][3] = p23[qm][2*kc+1];
            }
#pragma unroll
            for (int ng = 0; ng < 4; ng++) {
                uint32_t rr[4];
                ldsm_x4(rr, VbB + (ng * 16 + l15) * (KVPITCH*2) + kb);
#pragma unroll
                for (int qm = 0; qm < 2; qm++) {
                    mma_f16(oacc[qm][2*ng],   af[qm], rr[0], rr[2]);
                    mma_f16(oacc[qm][2*ng+1], af[qm], rr[1], rr[3]);
                }
            }
#pragma unroll
            for (int qm = 0; qm < 2; qm++)
                mma_f16(sumacc[qm], af[qm], ONES_H2, ONES_H2);
        }
        CP_WAIT0();
        __syncthreads();
    }

#pragma unroll
    for (int qm = 0; qm < 2; qm++) {
        float inv0 = 1.f / sumacc[qm][0];
        float inv1 = 1.f / sumacc[qm][2];
        size_t row0 = ((size_t)b * L_ + l0 + qb + qm*16 + g)     * C_ + h * HD_;
        size_t row1 = ((size_t)b * L_ + l0 + qb + qm*16 + g + 8) * C_ + h * HD_;
#pragma unroll
        for (int nt = 0; nt < 8; nt++) {
            int c = nt * 8 + 2 * t4;
            *(uint32_t*)&g_at[row0 + c] = f2bf2(oacc[qm][nt][0] * inv0,
                                                oacc[qm][nt][1] * inv0);
            *(uint32_t*)&g_at[row1 + c] = f2bf2(oacc[qm][nt][2] * inv1,
                                                oacc[qm][nt][3] * inv1);
        }
    }
}

// ---------------------------------------------------------------------------
extern "C" void kernel_launch(void* const* d_in, const int* in_sizes, int n_in,
                              void* d_out, int out_size)
{
    const float* x      = (const float*)d_in[0];
    const float* norm_w = (const float*)d_in[1];
    const float* norm_b = (const float*)d_in[2];
    const float* qkv_w  = (const float*)d_in[3];
    const float* qkv_b  = (const float*)d_in[4];
    const float* proj_w = (const float*)d_in[5];
    const float* proj_b = (const float*)d_in[6];
    float* out = (float*)d_out;

    cudaFuncSetAttribute(attn_kernel,
                         cudaFuncAttributeMaxDynamicSharedMemorySize, ATT_BYTES);
    cudaFuncSetAttribute(qkv_gemm_kernel,
                         cudaFuncAttributeMaxDynamicSharedMemorySize, GSMEM_BYTES);
    cudaFuncSetAttribute(proj_gemm_kernel,
                         cudaFuncAttributeMaxDynamicSharedMemorySize, GSMEM_BYTES);
    cudaFuncSetAttribute(gn_kernel,
                         cudaFuncAttributeMaxDynamicSharedMemorySize, GN_SMEM);

    gn_kernel<<<1536, 256, GN_SMEM>>>(x, norm_w, norm_b, qkv_w, proj_w);

    {
        dim3 grid(L_ / 128, M_QKV / 128, B_);
        qkv_gemm_kernel<<<grid, 256, GSMEM_BYTES>>>(qkv_b);
    }
    {
        dim3 grid(L_ / 128, B_ * NH_);
        attn_kernel<<<grid, 128, ATT_BYTES>>>();
    }
    {
        dim3 grid(L_ / 128, C_ / 128, B_);
        proj_gemm_kernel<<<grid, 256, GSMEM_BYTES>>>(proj_b, x, out);
    }
}